// round 15
// baseline (speedup 1.0000x reference)
#include <cuda_runtime.h>
#include <cuda_bf16.h>
#include <cstdint>

// ============================================================================
// ElementwiseTensorProducts — mma.sync.m16n8k16 bf16, 2-way split (hh+hl+lh).
//
// R15 changes vs R14 (223us):
//  * TOK 32 -> 64, 1 CTA/SM, warp grid 4 m16-tiles x 2 n64-halves (8 nt/warp):
//    A-fragment redundancy 4x -> 2x, W staging + barriers amortized over 2x
//    tokens: ~30% fewer crossbar bytes per token, half the syncs per token.
// Carried: weights pre-split once to __device__ scratch (prep kernel);
// W staging via cp.async.cg; W frags hoisted across the 3-irrep loop;
// A frags via ldmatrix.x4; register prefetch of gmem A one chunk ahead.
// ============================================================================

#define THREADS 256
#define TOK     64
#define SAU     20     // A tile stride (u32 pairs)
#define AIST    2560   // per-irrep A buffer stride (u32): hi 1280 + lo 1280
#define SWN     136    // W tile stride (u32 pairs): frag banks 8*qd+grp distinct
#define SP0F    140    // P0 stride (floats)
#define SP1F    396    // P1 stride (floats)

// smem byte offsets
#define OFF_A   0          // 3 x (hi 5120B + lo 5120B) = 30720
#define OFF_WH  30720      // 16*136*4 = 8704
#define OFF_WL  39424
#define OFF_P0  48128      // 64*140*4 = 35840
#define OFF_P1  83968      // 64*396*4 = 101376
#define SMEM_BYTES 185344

#define WTILE_U32 2176     // 16*136
__device__ __align__(16) uint32_t g_wh[18 * WTILE_U32];
__device__ __align__(16) uint32_t g_wl[18 * WTILE_U32];

__device__ __forceinline__ uint32_t pack2(float v0, float v1) {
    __nv_bfloat162 p = __floats2bfloat162_rn(v0, v1);   // v0 -> low half
    return *(uint32_t*)&p;
}

__device__ __forceinline__ void split_pair(float v0, float v1,
                                           uint32_t& h, uint32_t& l) {
    h = pack2(v0, v1);
    float h0 = __uint_as_float(h << 16);
    float h1 = __uint_as_float(h & 0xffff0000u);
    l = pack2(v0 - h0, v1 - h1);
}

// ---------------- prep kernel: split all 18 W chunk-tiles once ----------------
// tile 0-3: [W0l|W0r] k-slices; 4-7: [W1l|W1r]; 8-11: W0o; 12-17: W1o.
__global__ void prep_w_kernel(const float* __restrict__ W0l,
                              const float* __restrict__ W0r,
                              const float* __restrict__ W1l,
                              const float* __restrict__ W1r,
                              const float* __restrict__ W0o,
                              const float* __restrict__ W1o) {
    int e = blockIdx.x * blockDim.x + threadIdx.x;   // 0..36863
    int n    = e & 127;
    int kp   = (e >> 7) & 15;
    int tile = e >> 11;
    const float* src;
    int kb;
    if (tile < 4)       { kb = tile * 32;        src = (n < 64) ? W0l + n * 128 : W0r + (n - 64) * 128; }
    else if (tile < 8)  { kb = (tile - 4) * 32;  src = (n < 64) ? W1l + n * 128 : W1r + (n - 64) * 128; }
    else if (tile < 12) { kb = (tile - 8) * 32;  src = W0o + n * 128; }
    else                { kb = (tile - 12) * 32; src = W1o + n * 192; }
    float2 v = *(const float2*)(src + kb + 2 * kp);
    uint32_t h, l; split_pair(v.x, v.y, h, l);
    g_wh[tile * WTILE_U32 + kp * 136 + n] = h;
    g_wl[tile * WTILE_U32 + kp * 136 + n] = l;
}

// ---------------- main kernel helpers ----------------
__device__ __forceinline__ void mma16(float (&c)[4], const uint32_t (&a)[4],
                                      uint32_t b0, uint32_t b1) {
    asm volatile(
        "mma.sync.aligned.m16n8k16.row.col.f32.bf16.bf16.f32 "
        "{%0,%1,%2,%3}, {%4,%5,%6,%7}, {%8,%9}, {%0,%1,%2,%3};"
        : "+f"(c[0]), "+f"(c[1]), "+f"(c[2]), "+f"(c[3])
        : "r"(a[0]), "r"(a[1]), "r"(a[2]), "r"(a[3]), "r"(b0), "r"(b1));
}

__device__ __forceinline__ void ldsm_x4(uint32_t (&r)[4], const uint32_t* p) {
    uint32_t a = (uint32_t)__cvta_generic_to_shared(p);
    asm volatile("ldmatrix.sync.aligned.m8n8.x4.shared.b16 {%0,%1,%2,%3}, [%4];"
                 : "=r"(r[0]), "=r"(r[1]), "=r"(r[2]), "=r"(r[3]) : "r"(a));
}

// NI irreps per staged W chunk; 8 n-tiles per warp (n64 half). A frags via
// ldmatrix.x4; W frags loaded once per chunk and reused across irreps.
template <int NI>
__device__ __forceinline__ void gemm_chunk_multi(float (&acc)[NI][8][4],
        const uint32_t* __restrict__ aBase,
        const uint32_t* __restrict__ wH, const uint32_t* __restrict__ wL,
        int mrow0, int nb, int lane) {
    const int grp = lane >> 2, qd = lane & 3;
    const int ltok = mrow0 + (lane & 7) + ((lane >> 3) & 1) * 8;
    const int lkp  = (lane >> 4) * 4;
#pragma unroll
    for (int ks = 0; ks < 2; ++ks) {
        uint32_t ah[NI][4], al[NI][4];
#pragma unroll
        for (int i = 0; i < NI; ++i) {
            const uint32_t* ph = aBase + i * AIST + ltok * SAU + 8 * ks + lkp;
            ldsm_x4(ah[i], ph);
            ldsm_x4(al[i], ph + 1280);
        }
#pragma unroll
        for (int nt = 0; nt < 8; ++nt) {
            const uint32_t* pwh = wH + (8 * ks + qd) * SWN + nb + grp + 8 * nt;
            const uint32_t* pwl = wL + (8 * ks + qd) * SWN + nb + grp + 8 * nt;
            uint32_t bh0 = pwh[0], bh1 = pwh[4 * SWN];
            uint32_t bl0 = pwl[0], bl1 = pwl[4 * SWN];
#pragma unroll
            for (int i = 0; i < NI; ++i) {
                mma16(acc[i][nt], ah[i], bh0, bh1);
                mma16(acc[i][nt], ah[i], bl0, bl1);
                mma16(acc[i][nt], al[i], bh0, bh1);
            }
        }
    }
}

// Stage pre-split W tile via cp.async (16 rows x 32 uint4 used per buffer).
__device__ __forceinline__ void stage_W_cp(int tile,
                                           uint32_t* __restrict__ wH,
                                           uint32_t* __restrict__ wL, int tid) {
    const uint4* sh = (const uint4*)(g_wh + tile * WTILE_U32);
    const uint4* sl = (const uint4*)(g_wl + tile * WTILE_U32);
#pragma unroll
    for (int it = 0; it < 2; ++it) {
        int idx = tid + it * THREADS;        // 0..511 : row 0..15, quad 0..31
        int row = idx >> 5, q = idx & 31;
        uint32_t dh = (uint32_t)__cvta_generic_to_shared((uint4*)wH + row * 34 + q);
        uint32_t dl = (uint32_t)__cvta_generic_to_shared((uint4*)wL + row * 34 + q);
        asm volatile("cp.async.cg.shared.global [%0], [%1], 16;"
                     :: "r"(dh), "l"(sh + row * 34 + q));
        asm volatile("cp.async.cg.shared.global [%0], [%1], 16;"
                     :: "r"(dl), "l"(sl + row * 34 + q));
    }
}

#define CP_COMMIT_WAIT() do {                                     \
    asm volatile("cp.async.commit_group;" ::: "memory");          \
    asm volatile("cp.async.wait_group 0;" ::: "memory");          \
} while (0)

// -------- A staging: prefetch (LDG -> regs) + commit (split + STS) ---------
// 64 tok x 16 kp = 1024 elements, 4 per thread.
// e bits: [1:0]=kp_lo [4:2]=t_lo [6:5]=kp_hi [9:7]=t_hi (bijective).
__device__ __forceinline__ void prefetch_A(const float* __restrict__ src, int ld,
                                           float2 (&pre)[4], int tid) {
#pragma unroll
    for (int it = 0; it < 4; ++it) {
        int e  = tid + it * THREADS;                 // 0..1023
        int kp = (e & 3) | (((e >> 5) & 3) << 2);    // 0..15
        int t  = ((e >> 2) & 7) | ((e >> 7) << 3);   // 0..63
        pre[it] = *(const float2*)(src + (long)t * ld + 2 * kp);
    }
}

__device__ __forceinline__ void commit_A(const float2 (&pre)[4],
                                         uint32_t* __restrict__ aH,
                                         uint32_t* __restrict__ aL, int tid) {
#pragma unroll
    for (int it = 0; it < 4; ++it) {
        int e  = tid + it * THREADS;
        int kp = (e & 3) | (((e >> 5) & 3) << 2);
        int t  = ((e >> 2) & 7) | ((e >> 7) << 3);
        uint32_t h, l; split_pair(pre[it].x, pre[it].y, h, l);
        aH[t * SAU + kp] = h;
        aL[t * SAU + kp] = l;
    }
}

#define ZERO8(acc) do {                                      \
    _Pragma("unroll") for (int _n = 0; _n < 8; ++_n)         \
    _Pragma("unroll") for (int _m = 0; _m < 4; ++_m)         \
        (acc)[_n][_m] = 0.f;                                 \
} while (0)

__global__ __launch_bounds__(THREADS, 1)
void etp_bf16_kernel(const float* __restrict__ z0, const float* __restrict__ z1,
                     const float* __restrict__ b0l, const float* __restrict__ b0r,
                     const float* __restrict__ b0o,
                     float* __restrict__ out0, float* __restrict__ out1) {
    extern __shared__ char smem[];
    uint32_t* aBase = (uint32_t*)(smem + OFF_A);
    uint32_t* wH    = (uint32_t*)(smem + OFF_WH);
    uint32_t* wL    = (uint32_t*)(smem + OFF_WL);
    float*    sP0   = (float*)(smem + OFF_P0);
    float*    sP1   = (float*)(smem + OFF_P1);

    const int tid  = threadIdx.x;
    const int lane = tid & 31;
    const int warp = tid >> 5;
    const int grp  = lane >> 2, qd = lane & 3;
    const int mrow0 = (warp & 3) * 16;          // 4 m16-tiles
    const int nb    = (warp >> 2) * 64;         // 2 n64-halves
    const long tokbase = (long)blockIdx.x * TOK;

    uint32_t* aH0 = aBase;
    uint32_t* aL0 = aBase + 1280;

    float2 pre1[3][4];   // proj1 prefetch registers (live from end of proj0)

    // ================= proj0: P0 = z0 @ [W0l|W0r]^T + bias =================
    {
        float acc[1][8][4]; ZERO8(acc[0]);
        float2 pre0[4];
        prefetch_A(z0 + tokbase * 128, 128, pre0, tid);
        for (int c = 0; c < 4; ++c) {
            __syncthreads();
            stage_W_cp(c, wH, wL, tid);
            commit_A(pre0, aH0, aL0, tid);
            if (c < 3) {
                prefetch_A(z0 + tokbase * 128 + (c + 1) * 32, 128, pre0, tid);
            } else {
                // cross-phase: issue proj1 chunk-0 loads now
#pragma unroll
                for (int i = 0; i < 3; ++i)
                    prefetch_A(z1 + tokbase * 384 + i * 128, 384, pre1[i], tid);
            }
            CP_COMMIT_WAIT();
            __syncthreads();
            gemm_chunk_multi<1>(acc, aBase, wH, wL, mrow0, nb, lane);
        }
        const float* bp = nb ? (b0r - 64) : b0l;   // warp-uniform
#pragma unroll
        for (int nt = 0; nt < 8; ++nt) {
            int col = nb + nt * 8 + 2 * qd;
            float bx = bp[col], by = bp[col + 1];
            *(float2*)&sP0[(mrow0 + grp) * SP0F + col] =
                make_float2(acc[0][nt][0] + bx, acc[0][nt][1] + by);
            *(float2*)&sP0[(mrow0 + grp + 8) * SP0F + col] =
                make_float2(acc[0][nt][2] + bx, acc[0][nt][3] + by);
        }
    }

    // ====== proj1: P1_i = z1_i @ [W1l|W1r]^T  (one W chunk -> all 3 i) ======
    {
        float acc3[3][8][4];
#pragma unroll
        for (int i = 0; i < 3; ++i) ZERO8(acc3[i]);
        for (int c = 0; c < 4; ++c) {
            __syncthreads();
            stage_W_cp(4 + c, wH, wL, tid);
#pragma unroll
            for (int i = 0; i < 3; ++i)
                commit_A(pre1[i], aBase + i * AIST, aBase + i * AIST + 1280, tid);
            if (c < 3) {
#pragma unroll
                for (int i = 0; i < 3; ++i)
                    prefetch_A(z1 + tokbase * 384 + i * 128 + (c + 1) * 32, 384,
                               pre1[i], tid);
            }
            CP_COMMIT_WAIT();
            __syncthreads();
            gemm_chunk_multi<3>(acc3, aBase, wH, wL, mrow0, nb, lane);
        }
#pragma unroll
        for (int i = 0; i < 3; ++i)
#pragma unroll
            for (int nt = 0; nt < 8; ++nt) {
                int col = i * 128 + nb + nt * 8 + 2 * qd;
                *(float2*)&sP1[(mrow0 + grp) * SP1F + col] =
                    make_float2(acc3[i][nt][0], acc3[i][nt][1]);
                *(float2*)&sP1[(mrow0 + grp + 8) * SP1F + col] =
                    make_float2(acc3[i][nt][2], acc3[i][nt][3]);
            }
    }

    // ================= out0 = [p00 | p110] @ W0o^T + b0o =================
    {
        float acc[1][8][4]; ZERO8(acc[0]);
        for (int c = 0; c < 4; ++c) {
            __syncthreads();
            stage_W_cp(8 + c, wH, wL, tid);
            const int cb = c * 32;
#pragma unroll
            for (int it = 0; it < 4; ++it) {
                int e  = tid + it * THREADS;
                int kp = (e & 3) | (((e >> 5) & 3) << 2);
                int t  = ((e >> 2) & 7) | ((e >> 7) << 3);
                int k  = cb + 2 * kp;
                float v0, v1;
                if (cb < 64) {                            // p00 = P0l * P0r
                    const float* p = &sP0[t * SP0F];
                    v0 = p[k] * p[64 + k];
                    v1 = p[k + 1] * p[64 + k + 1];
                } else {                                  // p110 = sum_i P1l*P1r
                    int r = k - 64;
                    const float* p = &sP1[t * SP1F];
                    v0 = p[r] * p[64 + r] + p[128 + r] * p[192 + r]
                       + p[256 + r] * p[320 + r];
                    v1 = p[r + 1] * p[65 + r] + p[129 + r] * p[193 + r]
                       + p[257 + r] * p[321 + r];
                }
                uint32_t h, l; split_pair(v0, v1, h, l);
                aH0[t * SAU + kp] = h;
                aL0[t * SAU + kp] = l;
            }
            CP_COMMIT_WAIT();
            __syncthreads();
            gemm_chunk_multi<1>(acc, aBase, wH, wL, mrow0, nb, lane);
        }
#pragma unroll
        for (int nt = 0; nt < 8; ++nt) {
            int col = nb + nt * 8 + 2 * qd;
            float2 b = *(const float2*)&b0o[col];
            *(float2*)&out0[(tokbase + mrow0 + grp) * 128 + col] =
                make_float2(acc[0][nt][0] + b.x, acc[0][nt][1] + b.y);
            *(float2*)&out0[(tokbase + mrow0 + grp + 8) * 128 + col] =
                make_float2(acc[0][nt][2] + b.x, acc[0][nt][3] + b.y);
        }
    }

    // ==== out1_i = [q011|q101|q111]_i @ W1o^T  (one W chunk -> all 3 i) ====
    {
        float acc3[3][8][4];
#pragma unroll
        for (int i = 0; i < 3; ++i) ZERO8(acc3[i]);
        for (int cc = 0; cc < 6; ++cc) {
            __syncthreads();
            stage_W_cp(12 + cc, wH, wL, tid);
            const int cb = cc * 32;
#pragma unroll
            for (int i = 0; i < 3; ++i) {
                const int i1 = (i + 1 < 3) ? i + 1 : i - 2;
                const int i2 = (i + 2 < 3) ? i + 2 : i - 1;
                uint32_t* aH = aBase + i * AIST;
                uint32_t* aL = aH + 1280;
#pragma unroll
                for (int it = 0; it < 4; ++it) {
                    int e  = tid + it * THREADS;
                    int kp = (e & 3) | (((e >> 5) & 3) << 2);
                    int t  = ((e >> 2) & 7) | ((e >> 7) << 3);
                    int k  = cb + 2 * kp;
                    const float* p  = &sP1[t * SP1F];
                    const float* p0 = &sP0[t * SP0F];
                    float v0, v1;
                    if (cb < 64) {                        // q011 = P0l * P1r_i
                        v0 = p0[k] * p[i * 128 + 64 + k];
                        v1 = p0[k + 1] * p[i * 128 + 65 + k];
                    } else if (cb < 128) {                // q101 = P1l_i * P0r
                        int r = k - 64;
                        v0 = p[i * 128 + r] * p0[64 + r];
                        v1 = p[i * 128 + r + 1] * p0[65 + r];
                    } else {                              // q111 = cross_i
                        int r = k - 128;
                        v0 = p[i1 * 128 + r] * p[i2 * 128 + 64 + r]
                           - p[i2 * 128 + r] * p[i1 * 128 + 64 + r];
                        v1 = p[i1 * 128 + r + 1] * p[i2 * 128 + 65 + r]
                           - p[i2 * 128 + r + 1] * p[i1 * 128 + 65 + r];
                    }
                    uint32_t h, l; split_pair(v0, v1, h, l);
                    aH[t * SAU + kp] = h;
                    aL[t * SAU + kp] = l;
                }
            }
            CP_COMMIT_WAIT();
            __syncthreads();
            gemm_chunk_multi<3>(acc3, aBase, wH, wL, mrow0, nb, lane);
        }
#pragma unroll
        for (int i = 0; i < 3; ++i)
#pragma unroll
            for (int nt = 0; nt < 8; ++nt) {
                int col = nb + nt * 8 + 2 * qd;
                *(float2*)&out1[(tokbase + mrow0 + grp) * 384 + i * 128 + col] =
                    make_float2(acc3[i][nt][0], acc3[i][nt][1]);
                *(float2*)&out1[(tokbase + mrow0 + grp + 8) * 384 + i * 128 + col] =
                    make_float2(acc3[i][nt][2], acc3[i][nt][3]);
            }
    }
}

extern "C" void kernel_launch(void* const* d_in, const int* in_sizes, int n_in,
                              void* d_out, int out_size) {
    const float* z0  = (const float*)d_in[0];
    const float* z1  = (const float*)d_in[1];
    const float* W0l = (const float*)d_in[2];
    const float* b0l = (const float*)d_in[3];
    const float* W0r = (const float*)d_in[4];
    const float* b0r = (const float*)d_in[5];
    const float* W1l = (const float*)d_in[6];
    const float* W1r = (const float*)d_in[7];
    const float* W0o = (const float*)d_in[8];
    const float* b0o = (const float*)d_in[9];
    const float* W1o = (const float*)d_in[10];

    const int BN = in_sizes[0] / 128;            // 65536 tokens
    float* out0 = (float*)d_out;
    float* out1 = (float*)d_out + (long)BN * 128;

    prep_w_kernel<<<144, 256>>>(W0l, W0r, W1l, W1r, W0o, W1o);

    cudaFuncSetAttribute(etp_bf16_kernel,
                         cudaFuncAttributeMaxDynamicSharedMemorySize, SMEM_BYTES);

    dim3 grid(BN / TOK);    // 1024
    dim3 block(THREADS);
    etp_bf16_kernel<<<grid, block, SMEM_BYTES>>>(z0, z1, b0l, b0r, b0o,
                                                 out0, out1);
}